// round 13
// baseline (speedup 1.0000x reference)
#include <cuda_runtime.h>
#include <cuda_fp16.h>
#include <cstdint>

#define BATCH 2
#define HEADS 16
#define SEQ   4096
#define DIM   64
#define WIN   512
#define HALF  256
#define NSEG  16
#define BH    (BATCH*HEADS)

__device__ __align__(16) __half g_kh[(size_t)BH * SEQ * DIM];   // K fp16 [bh][s][d]
__device__ __align__(16) __half g_vt[(size_t)BH * DIM * SEQ];   // V fp16 transposed [bh][d][s]

#define KSTRIDE 72            // halves per smem row (64 data + 8 pad)
#define ROWB    144
#define TILE_B  (64*ROWB)     // 9216
#define STAGE_B (2*TILE_B)    // 18432
#define NSTAGE  2
#define XSTRIDE 66            // floats per stash row
#define XBUF_OFF   (NSTAGE*STAGE_B)                 // 36864
#define SMEM_BYTES (XBUF_OFF + 64*XSTRIDE*4)        // 53760 -> 4 CTAs/SM

#define ONE_H2 0x3C003C00u    // half2(1.0, 1.0)

__device__ __forceinline__ uint32_t pack_h2(float a, float b) {
    __half2 h = __floats2half2_rn(a, b);
    return *(uint32_t*)&h;
}
__device__ __forceinline__ void mma_f16(float c[4], const uint32_t a[4], uint32_t b0, uint32_t b1) {
    asm volatile(
        "mma.sync.aligned.m16n8k16.row.col.f32.f16.f16.f32 "
        "{%0,%1,%2,%3}, {%4,%5,%6,%7}, {%8,%9}, {%0,%1,%2,%3};"
        : "+f"(c[0]), "+f"(c[1]), "+f"(c[2]), "+f"(c[3])
        : "r"(a[0]), "r"(a[1]), "r"(a[2]), "r"(a[3]), "r"(b0), "r"(b1));
}
__device__ __forceinline__ uint32_t sigmoid_h2(float x0, float x1) {
    __half2 h = __floats2half2_rn(x0 * 0.5f, x1 * 0.5f);
    uint32_t t;
    asm("tanh.approx.f16x2 %0, %1;" : "=r"(t) : "r"(*(uint32_t*)&h));
    const __half2 c05 = __floats2half2_rn(0.5f, 0.5f);
    __half2 p = __hfma2(*(__half2*)&t, c05, c05);
    return *(uint32_t*)&p;
}
__device__ __forceinline__ uint32_t smem_u32(const void* p) {
    uint32_t a;
    asm("{ .reg .u64 t; cvta.to.shared.u64 t, %1; cvt.u32.u64 %0, t; }" : "=r"(a) : "l"(p));
    return a;
}
__device__ __forceinline__ void cp16(uint32_t dst, const void* src) {
    asm volatile("cp.async.cg.shared.global [%0], [%1], 16;" :: "r"(dst), "l"(src));
}

// ---------------- prep: K -> fp16, V -> fp16 transposed ----------------
__global__ __launch_bounds__(256)
void prep_kv(const float* __restrict__ K, const float* __restrict__ V)
{
    __shared__ float tile[32][65];
    const int bh = blockIdx.y;
    const int s0 = blockIdx.x * 32;
    const int tid = threadIdx.x;

    const float* ks = K + ((size_t)bh * SEQ + s0) * DIM;
    const float* vs = V + ((size_t)bh * SEQ + s0) * DIM;
    __half* kd = g_kh + ((size_t)bh * SEQ + s0) * DIM;

    #pragma unroll
    for (int i = 0; i < 8; i++) {
        int w = tid + i * 256;
        int s = w >> 6, d = w & 63;
        kd[w] = __float2half_rn(ks[w]);
        tile[s][d] = vs[w];
    }
    __syncthreads();
    #pragma unroll
    for (int i = 0; i < 8; i++) {
        int w = tid + i * 256;
        int d = w >> 5, s = w & 31;
        g_vt[((size_t)bh * DIM + d) * SEQ + s0 + s] = __float2half_rn(tile[s][d]);
    }
}

// ---------------- fused attention + blend, 3-phase, den-by-MMA, 4 CTAs/SM ----------------
__global__ __launch_bounds__(128, 4)
void win_attn_p(const float* __restrict__ Q,
                const float* __restrict__ scale_p,
                float* __restrict__ out)
{
    extern __shared__ __align__(16) char dsm[];
    const uint32_t sbase = smem_u32(dsm);
    float* xbuf = (float*)(dsm + XBUF_OFF);

    const int tid  = threadIdx.x;
    const int lane = tid & 31;
    const int warp = tid >> 5;          // 0..3, rows [warp*16, warp*16+16)
    const int gid  = lane >> 2;
    const int tig  = lane & 3;

    const int bh = blockIdx.y;
    const int k  = blockIdx.x >> 2;
    const int qt = blockIdx.x & 3;

    const int key_base = (k == 0) ? 0 : (k - 1) * HALF;
    const int nchunks  = (k == 0 || k == NSEG - 1) ? 8 : 12;
    const int q0s      = k * HALF + qt * 64;
    const float scale  = *scale_p;

    const char* kh_bh = (const char*)(g_kh + (size_t)bh * SEQ * DIM);
    const char* vt_bh = (const char*)(g_vt + (size_t)bh * DIM * SEQ);

    auto issue = [&](int cc, int st) {
        const uint32_t sb = sbase + st * STAGE_B;
        const char* kg = kh_bh + (size_t)(key_base + cc * 64) * 128;
        const char* vg = vt_bh + (size_t)(key_base + cc * 64) * 2;
        #pragma unroll
        for (int i = 0; i < 4; i++) {
            int idx = tid + i * 128;
            int r = idx >> 3, c16 = (idx & 7) * 16;
            cp16(sb + r * ROWB + c16,          kg + r * 128 + c16);
            cp16(sb + TILE_B + r * ROWB + c16, vg + (size_t)r * 8192 + c16);
        }
    };

    // ---- Q fragments (m16n8k16 A), fp16, scale folded in ----
    uint32_t qa[4][4];
    {
        const size_t base = (size_t)bh * SEQ * DIM;
        const float* q0 = Q + base + (size_t)(q0s + warp * 16 + gid) * DIM;
        const float* q1 = q0 + 8 * DIM;
        #pragma unroll
        for (int ks = 0; ks < 4; ks++) {
            float2 v;
            v = *(const float2*)(q0 + ks * 16 + 2 * tig);
            qa[ks][0] = pack_h2(v.x * scale, v.y * scale);
            v = *(const float2*)(q1 + ks * 16 + 2 * tig);
            qa[ks][1] = pack_h2(v.x * scale, v.y * scale);
            v = *(const float2*)(q0 + ks * 16 + 2 * tig + 8);
            qa[ks][2] = pack_h2(v.x * scale, v.y * scale);
            v = *(const float2*)(q1 + ks * 16 + 2 * tig + 8);
            qa[ks][3] = pack_h2(v.x * scale, v.y * scale);
        }
    }

    const int i0 = qt * 64 + warp * 16 + gid;
    const float a0 = (float)i0 * (1.0f / 255.0f);
    const float a1 = (float)(i0 + 8) * (1.0f / 255.0f);

    issue(0, 0);
    asm volatile("cp.async.commit_group;" ::: "memory");

    float dacc[8][4];
    #pragma unroll
    for (int nt = 0; nt < 8; nt++)
        #pragma unroll
        for (int i = 0; i < 4; i++) dacc[nt][i] = 0.0f;
    float dden[4] = {0.0f, 0.0f, 0.0f, 0.0f};   // row-sum accumulator via ones-MMA
    float s3_0 = 0.0f, s3_1 = 0.0f;             // dden snapshot after chunk 3

    const int brow = gid * (KSTRIDE / 2) + tig;
    const int lr0 = warp * 16 + gid;
    const int lr1 = lr0 + 8;

    for (int c = 0; c < nchunks; c++) {
        asm volatile("cp.async.wait_group 0;" ::: "memory");
        __syncthreads();                // chunk c resident; all warps past chunk c-1

        const int st = c & 1;
        const uint32_t* sKu = (const uint32_t*)(dsm + st * STAGE_B);
        const uint32_t* sVu = (const uint32_t*)(dsm + st * STAGE_B + TILE_B);

        if (c + 1 < nchunks) {
            issue(c + 1, (c + 1) & 1);
            asm volatile("cp.async.commit_group;" ::: "memory");
        }

        // ---- phase A: all 8 MMA1 chains (independent) + sigmoid -> pa ----
        uint32_t pa[4][4];
        #pragma unroll
        for (int nt = 0; nt < 8; nt++) {
            float sl[4] = {0.0f, 0.0f, 0.0f, 0.0f};
            const int rb = nt * 8 * (KSTRIDE / 2) + brow;
            #pragma unroll
            for (int ks = 0; ks < 4; ks++)
                mma_f16(sl, qa[ks], sKu[rb + 8 * ks], sKu[rb + 8 * ks + 4]);
            const int kc = nt >> 1, hi = (nt & 1) * 2;
            pa[kc][hi]     = sigmoid_h2(sl[0], sl[1]);
            pa[kc][hi + 1] = sigmoid_h2(sl[2], sl[3]);
        }

        // ---- phase B: MMA2 (8 independent dacc chains) + denominator MMA ----
        #pragma unroll
        for (int kc = 0; kc < 4; kc++) {
            #pragma unroll
            for (int nt = 0; nt < 8; nt++) {
                const int rb = nt * 8 * (KSTRIDE / 2) + brow;
                mma_f16(dacc[nt], pa[kc], sVu[rb + 8 * kc], sVu[rb + 8 * kc + 4]);
            }
            mma_f16(dden, pa[kc], ONE_H2, ONE_H2);   // den += P . 1
        }

        if (k > 0) {
            if (c == 3) {
                // snapshot den(0..3); stash D_prevonly; restart accumulator
                s3_0 = dden[0];
                s3_1 = dden[2];
                #pragma unroll
                for (int nt = 0; nt < 8; nt++) {
                    *(float2*)(xbuf + lr0 * XSTRIDE + nt * 8 + 2 * tig) = make_float2(dacc[nt][0], dacc[nt][1]);
                    *(float2*)(xbuf + lr1 * XSTRIDE + nt * 8 + 2 * tig) = make_float2(dacc[nt][2], dacc[nt][3]);
                    dacc[nt][0] = 0.0f; dacc[nt][1] = 0.0f; dacc[nt][2] = 0.0f; dacc[nt][3] = 0.0f;
                }
            } else if (c == 7) {
                // denp = den(0..7) complete: fold prev into stash
                const float wp0 = (1.0f - a0) / dden[0];
                const float wp1 = (1.0f - a1) / dden[2];
                #pragma unroll
                for (int nt = 0; nt < 8; nt++) {
                    float2 s0 = *(const float2*)(xbuf + lr0 * XSTRIDE + nt * 8 + 2 * tig);
                    float2 s1 = *(const float2*)(xbuf + lr1 * XSTRIDE + nt * 8 + 2 * tig);
                    s0.x = wp0 * (s0.x + dacc[nt][0]);
                    s0.y = wp0 * (s0.y + dacc[nt][1]);
                    s1.x = wp1 * (s1.x + dacc[nt][2]);
                    s1.y = wp1 * (s1.y + dacc[nt][3]);
                    *(float2*)(xbuf + lr0 * XSTRIDE + nt * 8 + 2 * tig) = s0;
                    *(float2*)(xbuf + lr1 * XSTRIDE + nt * 8 + 2 * tig) = s1;
                }
            }
        }
    }

    float* o0 = out + ((size_t)bh * SEQ + q0s + warp * 16 + gid) * DIM;
    float* o1 = o0 + 8 * DIM;

    if (k == 0) {
        const float inv0 = 1.0f / dden[0];
        const float inv1 = 1.0f / dden[2];
        #pragma unroll
        for (int nt = 0; nt < 8; nt++) {
            *(float2*)(o0 + nt * 8 + 2 * tig) = make_float2(dacc[nt][0] * inv0, dacc[nt][1] * inv0);
            *(float2*)(o1 + nt * 8 + 2 * tig) = make_float2(dacc[nt][2] * inv1, dacc[nt][3] * inv1);
        }
    } else {
        // denn = den(4..end) = den_total - den(0..3)
        const float wn0 = a0 / (dden[0] - s3_0);
        const float wn1 = a1 / (dden[2] - s3_1);
        #pragma unroll
        for (int nt = 0; nt < 8; nt++) {
            float2 s0 = *(const float2*)(xbuf + lr0 * XSTRIDE + nt * 8 + 2 * tig);
            float2 s1 = *(const float2*)(xbuf + lr1 * XSTRIDE + nt * 8 + 2 * tig);
            float2 r0 = { s0.x + wn0 * dacc[nt][0], s0.y + wn0 * dacc[nt][1] };
            float2 r1 = { s1.x + wn1 * dacc[nt][2], s1.y + wn1 * dacc[nt][3] };
            *(float2*)(o0 + nt * 8 + 2 * tig) = r0;
            *(float2*)(o1 + nt * 8 + 2 * tig) = r1;
        }
    }
}

extern "C" void kernel_launch(void* const* d_in, const int* in_sizes, int n_in,
                              void* d_out, int out_size)
{
    const float* Q     = (const float*)d_in[0];
    const float* K     = (const float*)d_in[1];
    const float* V     = (const float*)d_in[2];
    const float* scale = (const float*)d_in[3];
    float* out = (float*)d_out;

    static bool attr_set = false;
    if (!attr_set) {
        cudaFuncSetAttribute(win_attn_p, cudaFuncAttributeMaxDynamicSharedMemorySize, SMEM_BYTES);
        attr_set = true;
    }

    dim3 pgrid(SEQ / 32, BH);
    prep_kv<<<pgrid, 256>>>(K, V);

    dim3 grid(NSEG * 4, BH);
    win_attn_p<<<grid, 128, SMEM_BYTES>>>(Q, scale, out);
}

// round 14
// speedup vs baseline: 1.0690x; 1.0690x over previous
#include <cuda_runtime.h>
#include <cuda_fp16.h>
#include <cstdint>

#define BATCH 2
#define HEADS 16
#define SEQ   4096
#define DIM   64
#define WIN   512
#define HALF  256
#define NSEG  16
#define BH    (BATCH*HEADS)

__device__ __align__(16) __half g_kh[(size_t)BH * SEQ * DIM];   // K fp16 [bh][s][d]
__device__ __align__(16) __half g_vt[(size_t)BH * DIM * SEQ];   // V fp16 transposed [bh][d][s]

#define KSTRIDE 72            // halves per smem row (64 data + 8 pad)
#define ROWB    144
#define TILE_B  (64*ROWB)     // 9216
#define STAGE_B (2*TILE_B)    // 18432
#define NSTAGE  2
#define XSTRIDE 66            // floats per stash row
#define XBUF_OFF   (NSTAGE*STAGE_B)                  // 36864
#define SMEM_BYTES (XBUF_OFF + 128*XSTRIDE*4)        // 70656 -> 3 CTAs/SM

#define ONE_H2 0x3C003C00u    // half2(1.0, 1.0)

__device__ __forceinline__ uint32_t pack_h2(float a, float b) {
    __half2 h = __floats2half2_rn(a, b);
    return *(uint32_t*)&h;
}
__device__ __forceinline__ void mma_f16(float c[4], const uint32_t a[4], uint32_t b0, uint32_t b1) {
    asm volatile(
        "mma.sync.aligned.m16n8k16.row.col.f32.f16.f16.f32 "
        "{%0,%1,%2,%3}, {%4,%5,%6,%7}, {%8,%9}, {%0,%1,%2,%3};"
        : "+f"(c[0]), "+f"(c[1]), "+f"(c[2]), "+f"(c[3])
        : "r"(a[0]), "r"(a[1]), "r"(a[2]), "r"(a[3]), "r"(b0), "r"(b1));
}
__device__ __forceinline__ uint32_t sigmoid_h2(float x0, float x1) {
    __half2 h = __floats2half2_rn(x0 * 0.5f, x1 * 0.5f);
    uint32_t t;
    asm("tanh.approx.f16x2 %0, %1;" : "=r"(t) : "r"(*(uint32_t*)&h));
    const __half2 c05 = __floats2half2_rn(0.5f, 0.5f);
    __half2 p = __hfma2(*(__half2*)&t, c05, c05);
    return *(uint32_t*)&p;
}
__device__ __forceinline__ uint32_t smem_u32(const void* p) {
    uint32_t a;
    asm("{ .reg .u64 t; cvta.to.shared.u64 t, %1; cvt.u32.u64 %0, t; }" : "=r"(a) : "l"(p));
    return a;
}
__device__ __forceinline__ void cp16(uint32_t dst, const void* src) {
    asm volatile("cp.async.cg.shared.global [%0], [%1], 16;" :: "r"(dst), "l"(src));
}

// ---------------- prep: K -> fp16, V -> fp16 transposed ----------------
__global__ __launch_bounds__(256)
void prep_kv(const float* __restrict__ K, const float* __restrict__ V)
{
    __shared__ float tile[32][65];
    const int bh = blockIdx.y;
    const int s0 = blockIdx.x * 32;
    const int tid = threadIdx.x;

    const float* ks = K + ((size_t)bh * SEQ + s0) * DIM;
    const float* vs = V + ((size_t)bh * SEQ + s0) * DIM;
    __half* kd = g_kh + ((size_t)bh * SEQ + s0) * DIM;

    #pragma unroll
    for (int i = 0; i < 8; i++) {
        int w = tid + i * 256;
        int s = w >> 6, d = w & 63;
        kd[w] = __float2half_rn(ks[w]);
        tile[s][d] = vs[w];
    }
    __syncthreads();
    #pragma unroll
    for (int i = 0; i < 8; i++) {
        int w = tid + i * 256;
        int d = w >> 5, s = w & 31;
        g_vt[((size_t)bh * DIM + d) * SEQ + s0 + s] = __float2half_rn(tile[s][d]);
    }
}

// ---------------- fused attention + blend, M=32 rows/warp ----------------
// CTA = 128 threads = 4 warps x 32 query rows = 128 outputs. Each smem K/V
// fragment load feeds TWO row-block MMAs (halves smem B-traffic per output).
__global__ __launch_bounds__(128, 3)
void win_attn_m(const float* __restrict__ Q,
                const float* __restrict__ scale_p,
                float* __restrict__ out)
{
    extern __shared__ __align__(16) char dsm[];
    const uint32_t sbase = smem_u32(dsm);
    float* xbuf = (float*)(dsm + XBUF_OFF);

    const int tid  = threadIdx.x;
    const int lane = tid & 31;
    const int warp = tid >> 5;          // 0..3, rows [warp*32, warp*32+32)
    const int gid  = lane >> 2;
    const int tig  = lane & 3;

    const int bh = blockIdx.y;
    const int k  = blockIdx.x >> 1;     // segment 0..15
    const int qt = blockIdx.x & 1;      // 128-row tile within segment

    const int key_base = (k == 0) ? 0 : (k - 1) * HALF;
    const int nchunks  = (k == 0 || k == NSEG - 1) ? 8 : 12;
    const int q0s      = k * HALF + qt * 128;
    const float scale  = *scale_p;

    const char* kh_bh = (const char*)(g_kh + (size_t)bh * SEQ * DIM);
    const char* vt_bh = (const char*)(g_vt + (size_t)bh * DIM * SEQ);

    auto issue = [&](int cc, int st) {
        const uint32_t sb = sbase + st * STAGE_B;
        const char* kg = kh_bh + (size_t)(key_base + cc * 64) * 128;
        const char* vg = vt_bh + (size_t)(key_base + cc * 64) * 2;
        #pragma unroll
        for (int i = 0; i < 4; i++) {
            int idx = tid + i * 128;
            int r = idx >> 3, c16 = (idx & 7) * 16;
            cp16(sb + r * ROWB + c16,          kg + r * 128 + c16);
            cp16(sb + TILE_B + r * ROWB + c16, vg + (size_t)r * 8192 + c16);
        }
    };

    // ---- Q fragments for two 16-row blocks (scale folded in) ----
    uint32_t qa[2][4][4];
    {
        const size_t base = (size_t)bh * SEQ * DIM;
        #pragma unroll
        for (int b = 0; b < 2; b++) {
            const float* q0 = Q + base + (size_t)(q0s + warp * 32 + b * 16 + gid) * DIM;
            const float* q1 = q0 + 8 * DIM;
            #pragma unroll
            for (int ks = 0; ks < 4; ks++) {
                float2 v;
                v = *(const float2*)(q0 + ks * 16 + 2 * tig);
                qa[b][ks][0] = pack_h2(v.x * scale, v.y * scale);
                v = *(const float2*)(q1 + ks * 16 + 2 * tig);
                qa[b][ks][1] = pack_h2(v.x * scale, v.y * scale);
                v = *(const float2*)(q0 + ks * 16 + 2 * tig + 8);
                qa[b][ks][2] = pack_h2(v.x * scale, v.y * scale);
                v = *(const float2*)(q1 + ks * 16 + 2 * tig + 8);
                qa[b][ks][3] = pack_h2(v.x * scale, v.y * scale);
            }
        }
    }

    const int i0 = qt * 128 + warp * 32 + gid;         // row-block0 low row
    const float aw[4] = { (float)i0        * (1.0f / 255.0f),
                          (float)(i0 + 8)  * (1.0f / 255.0f),
                          (float)(i0 + 16) * (1.0f / 255.0f),
                          (float)(i0 + 24) * (1.0f / 255.0f) };

    issue(0, 0);
    asm volatile("cp.async.commit_group;" ::: "memory");

    float dacc[2][8][4];
    #pragma unroll
    for (int b = 0; b < 2; b++)
        #pragma unroll
        for (int nt = 0; nt < 8; nt++)
            #pragma unroll
            for (int i = 0; i < 4; i++) dacc[b][nt][i] = 0.0f;
    float dden[2][4] = {{0,0,0,0},{0,0,0,0}};
    float s3[4] = {0,0,0,0};            // dden snapshots after chunk 3

    const int brow = gid * (KSTRIDE / 2) + tig;
    const int lrw  = warp * 32 + gid;   // stash row base

    for (int c = 0; c < nchunks; c++) {
        asm volatile("cp.async.wait_group 0;" ::: "memory");
        __syncthreads();

        const int st = c & 1;
        const uint32_t* sKu = (const uint32_t*)(dsm + st * STAGE_B);
        const uint32_t* sVu = (const uint32_t*)(dsm + st * STAGE_B + TILE_B);

        if (c + 1 < nchunks) {
            issue(c + 1, (c + 1) & 1);
            asm volatile("cp.async.commit_group;" ::: "memory");
        }

        // ---- phase A: MMA1 for both row-blocks, fragments loaded once ----
        uint32_t pa[2][4][4];
        #pragma unroll
        for (int nt = 0; nt < 8; nt++) {
            float sl0[4] = {0,0,0,0}, sl1[4] = {0,0,0,0};
            const int rb = nt * 8 * (KSTRIDE / 2) + brow;
            #pragma unroll
            for (int ks = 0; ks < 4; ks++) {
                const uint32_t b0 = sKu[rb + 8 * ks];
                const uint32_t b1 = sKu[rb + 8 * ks + 4];
                mma_f16(sl0, qa[0][ks], b0, b1);
                mma_f16(sl1, qa[1][ks], b0, b1);
            }
            const int kc = nt >> 1, hi = (nt & 1) * 2;
            pa[0][kc][hi]     = sigmoid_h2(sl0[0], sl0[1]);
            pa[0][kc][hi + 1] = sigmoid_h2(sl0[2], sl0[3]);
            pa[1][kc][hi]     = sigmoid_h2(sl1[0], sl1[1]);
            pa[1][kc][hi + 1] = sigmoid_h2(sl1[2], sl1[3]);
        }

        // ---- phase B: MMA2 for both row-blocks + denominator MMAs ----
        #pragma unroll
        for (int kc = 0; kc < 4; kc++) {
            #pragma unroll
            for (int nt = 0; nt < 8; nt++) {
                const int rb = nt * 8 * (KSTRIDE / 2) + brow;
                const uint32_t b0 = sVu[rb + 8 * kc];
                const uint32_t b1 = sVu[rb + 8 * kc + 4];
                mma_f16(dacc[0][nt], pa[0][kc], b0, b1);
                mma_f16(dacc[1][nt], pa[1][kc], b0, b1);
            }
            mma_f16(dden[0], pa[0][kc], ONE_H2, ONE_H2);
            mma_f16(dden[1], pa[1][kc], ONE_H2, ONE_H2);
        }

        if (k > 0) {
            if (c == 3) {
                s3[0] = dden[0][0]; s3[1] = dden[0][2];
                s3[2] = dden[1][0]; s3[3] = dden[1][2];
                #pragma unroll
                for (int b = 0; b < 2; b++)
                    #pragma unroll
                    for (int nt = 0; nt < 8; nt++) {
                        const int r0 = lrw + b * 16, r1 = r0 + 8;
                        *(float2*)(xbuf + r0 * XSTRIDE + nt * 8 + 2 * tig) = make_float2(dacc[b][nt][0], dacc[b][nt][1]);
                        *(float2*)(xbuf + r1 * XSTRIDE + nt * 8 + 2 * tig) = make_float2(dacc[b][nt][2], dacc[b][nt][3]);
                        dacc[b][nt][0] = 0.0f; dacc[b][nt][1] = 0.0f;
                        dacc[b][nt][2] = 0.0f; dacc[b][nt][3] = 0.0f;
                    }
            } else if (c == 7) {
                const float wp[4] = { (1.0f - aw[0]) / dden[0][0],
                                      (1.0f - aw[1]) / dden[0][2],
                                      (1.0f - aw[2]) / dden[1][0],
                                      (1.0f - aw[3]) / dden[1][2] };
                #pragma unroll
                for (int b = 0; b < 2; b++)
                    #pragma unroll
                    for (int nt = 0; nt < 8; nt++) {
                        const int r0 = lrw + b * 16, r1 = r0 + 8;
                        float2 s0 = *(const float2*)(xbuf + r0 * XSTRIDE + nt * 8 + 2 * tig);
                        float2 s1 = *(const float2*)(xbuf + r1 * XSTRIDE + nt * 8 + 2 * tig);
                        s0.x = wp[2*b]   * (s0.x + dacc[b][nt][0]);
                        s0.y = wp[2*b]   * (s0.y + dacc[b][nt][1]);
                        s1.x = wp[2*b+1] * (s1.x + dacc[b][nt][2]);
                        s1.y = wp[2*b+1] * (s1.y + dacc[b][nt][3]);
                        *(float2*)(xbuf + r0 * XSTRIDE + nt * 8 + 2 * tig) = s0;
                        *(float2*)(xbuf + r1 * XSTRIDE + nt * 8 + 2 * tig) = s1;
                    }
            }
        }
    }

    if (k == 0) {
        #pragma unroll
        for (int b = 0; b < 2; b++) {
            float* o0 = out + ((size_t)bh * SEQ + q0s + warp * 32 + b * 16 + gid) * DIM;
            float* o1 = o0 + 8 * DIM;
            const float inv0 = 1.0f / dden[b][0];
            const float inv1 = 1.0f / dden[b][2];
            #pragma unroll
            for (int nt = 0; nt < 8; nt++) {
                *(float2*)(o0 + nt * 8 + 2 * tig) = make_float2(dacc[b][nt][0] * inv0, dacc[b][nt][1] * inv0);
                *(float2*)(o1 + nt * 8 + 2 * tig) = make_float2(dacc[b][nt][2] * inv1, dacc[b][nt][3] * inv1);
            }
        }
    } else {
        const float wn[4] = { aw[0] / (dden[0][0] - s3[0]),
                              aw[1] / (dden[0][2] - s3[1]),
                              aw[2] / (dden[1][0] - s3[2]),
                              aw[3] / (dden[1][2] - s3[3]) };
        #pragma unroll
        for (int b = 0; b < 2; b++) {
            float* o0 = out + ((size_t)bh * SEQ + q0s + warp * 32 + b * 16 + gid) * DIM;
            float* o1 = o0 + 8 * DIM;
            const int r0 = lrw + b * 16, r1 = r0 + 8;
            #pragma unroll
            for (int nt = 0; nt < 8; nt++) {
                float2 s0 = *(const float2*)(xbuf + r0 * XSTRIDE + nt * 8 + 2 * tig);
                float2 s1 = *(const float2*)(xbuf + r1 * XSTRIDE + nt * 8 + 2 * tig);
                float2 out0 = { s0.x + wn[2*b]   * dacc[b][nt][0], s0.y + wn[2*b]   * dacc[b][nt][1] };
                float2 out1 = { s1.x + wn[2*b+1] * dacc[b][nt][2], s1.y + wn[2*b+1] * dacc[b][nt][3] };
                *(float2*)(o0 + nt * 8 + 2 * tig) = out0;
                *(float2*)(o1 + nt * 8 + 2 * tig) = out1;
            }
        }
    }
}

extern "C" void kernel_launch(void* const* d_in, const int* in_sizes, int n_in,
                              void* d_out, int out_size)
{
    const float* Q     = (const float*)d_in[0];
    const float* K     = (const float*)d_in[1];
    const float* V     = (const float*)d_in[2];
    const float* scale = (const float*)d_in[3];
    float* out = (float*)d_out;

    static bool attr_set = false;
    if (!attr_set) {
        cudaFuncSetAttribute(win_attn_m, cudaFuncAttributeMaxDynamicSharedMemorySize, SMEM_BYTES);
        attr_set = true;
    }

    dim3 pgrid(SEQ / 32, BH);
    prep_kv<<<pgrid, 256>>>(K, V);

    dim3 grid(NSEG * 2, BH);
    win_attn_m<<<grid, 128, SMEM_BYTES>>>(Q, scale, out);
}

// round 15
// speedup vs baseline: 1.1761x; 1.1002x over previous
#include <cuda_runtime.h>
#include <cuda_fp16.h>
#include <cstdint>

#define BATCH 2
#define HEADS 16
#define SEQ   4096
#define DIM   64
#define WIN   512
#define HALF  256
#define NSEG  16
#define BH    (BATCH*HEADS)

__device__ __align__(16) __half g_kh[(size_t)BH * SEQ * DIM];   // K fp16 [bh][s][d]
__device__ __align__(16) __half g_vt[(size_t)BH * DIM * SEQ];   // V fp16 transposed [bh][d][s]

#define KSTRIDE 72            // halves per smem row (64 data + 8 pad)
#define ROWB    144
#define TILE_B  (64*ROWB)     // 9216
#define STAGE_B (2*TILE_B)    // 18432
#define NSTAGE  3
#define XSTRIDE_W 34          // half2 words per stash row (32 data + 2 pad)
#define XBUF_OFF   (NSTAGE*STAGE_B)                    // 55296
#define SMEM_BYTES (XBUF_OFF + 128*XSTRIDE_W*4)        // 72704 -> 3 CTAs/SM

#define ONE_H2 0x3C003C00u    // half2(1.0, 1.0)

__device__ __forceinline__ uint32_t pack_h2(float a, float b) {
    __half2 h = __floats2half2_rn(a, b);
    return *(uint32_t*)&h;
}
__device__ __forceinline__ void mma_f16(float c[4], const uint32_t a[4], uint32_t b0, uint32_t b1) {
    asm volatile(
        "mma.sync.aligned.m16n8k16.row.col.f32.f16.f16.f32 "
        "{%0,%1,%2,%3}, {%4,%5,%6,%7}, {%8,%9}, {%0,%1,%2,%3};"
        : "+f"(c[0]), "+f"(c[1]), "+f"(c[2]), "+f"(c[3])
        : "r"(a[0]), "r"(a[1]), "r"(a[2]), "r"(a[3]), "r"(b0), "r"(b1));
}
__device__ __forceinline__ uint32_t sigmoid_h2(float x0, float x1) {
    __half2 h = __floats2half2_rn(x0 * 0.5f, x1 * 0.5f);
    uint32_t t;
    asm("tanh.approx.f16x2 %0, %1;" : "=r"(t) : "r"(*(uint32_t*)&h));
    const __half2 c05 = __floats2half2_rn(0.5f, 0.5f);
    __half2 p = __hfma2(*(__half2*)&t, c05, c05);
    return *(uint32_t*)&p;
}
__device__ __forceinline__ uint32_t smem_u32(const void* p) {
    uint32_t a;
    asm("{ .reg .u64 t; cvta.to.shared.u64 t, %1; cvt.u32.u64 %0, t; }" : "=r"(a) : "l"(p));
    return a;
}
__device__ __forceinline__ void cp16(uint32_t dst, const void* src) {
    asm volatile("cp.async.cg.shared.global [%0], [%1], 16;" :: "r"(dst), "l"(src));
}

// ---------------- prep: K -> fp16, V -> fp16 transposed ----------------
__global__ __launch_bounds__(256)
void prep_kv(const float* __restrict__ K, const float* __restrict__ V)
{
    __shared__ float tile[32][65];
    const int bh = blockIdx.y;
    const int s0 = blockIdx.x * 32;
    const int tid = threadIdx.x;

    const float* ks = K + ((size_t)bh * SEQ + s0) * DIM;
    const float* vs = V + ((size_t)bh * SEQ + s0) * DIM;
    __half* kd = g_kh + ((size_t)bh * SEQ + s0) * DIM;

    #pragma unroll
    for (int i = 0; i < 8; i++) {
        int w = tid + i * 256;
        int s = w >> 6, d = w & 63;
        kd[w] = __float2half_rn(ks[w]);
        tile[s][d] = vs[w];
    }
    __syncthreads();
    #pragma unroll
    for (int i = 0; i < 8; i++) {
        int w = tid + i * 256;
        int d = w >> 5, s = w & 31;
        g_vt[((size_t)bh * DIM + d) * SEQ + s0 + s] = __float2half_rn(tile[s][d]);
    }
}

// ---------------- fused attention + blend, M=32/warp, depth-2 pipeline ----------------
__global__ __launch_bounds__(128, 3)
void win_attn_m(const float* __restrict__ Q,
                const float* __restrict__ scale_p,
                float* __restrict__ out)
{
    extern __shared__ __align__(16) char dsm[];
    const uint32_t sbase = smem_u32(dsm);
    uint32_t* xbuf = (uint32_t*)(dsm + XBUF_OFF);   // fp16x2 stash

    const int tid  = threadIdx.x;
    const int lane = tid & 31;
    const int warp = tid >> 5;          // 0..3, rows [warp*32, warp*32+32)
    const int gid  = lane >> 2;
    const int tig  = lane & 3;

    const int bh = blockIdx.y;
    const int kk = blockIdx.x >> 1;
    // schedule 12-chunk segments first, 8-chunk (k=0,15) last (wave-tail balance)
    const int k  = (kk < 14) ? (kk + 1) : ((kk == 14) ? 0 : 15);
    const int qt = blockIdx.x & 1;      // 128-row tile within segment

    const int key_base = (k == 0) ? 0 : (k - 1) * HALF;
    const int nchunks  = (k == 0 || k == NSEG - 1) ? 8 : 12;
    const int q0s      = k * HALF + qt * 128;
    const float scale  = *scale_p;

    const char* kh_bh = (const char*)(g_kh + (size_t)bh * SEQ * DIM);
    const char* vt_bh = (const char*)(g_vt + (size_t)bh * DIM * SEQ);

    auto issue = [&](int cc, int st) {
        const uint32_t sb = sbase + st * STAGE_B;
        const char* kg = kh_bh + (size_t)(key_base + cc * 64) * 128;
        const char* vg = vt_bh + (size_t)(key_base + cc * 64) * 2;
        #pragma unroll
        for (int i = 0; i < 4; i++) {
            int idx = tid + i * 128;
            int r = idx >> 3, c16 = (idx & 7) * 16;
            cp16(sb + r * ROWB + c16,          kg + r * 128 + c16);
            cp16(sb + TILE_B + r * ROWB + c16, vg + (size_t)r * 8192 + c16);
        }
    };

    // ---- Q fragments for two 16-row blocks (scale folded in) ----
    uint32_t qa[2][4][4];
    {
        const size_t base = (size_t)bh * SEQ * DIM;
        #pragma unroll
        for (int b = 0; b < 2; b++) {
            const float* q0 = Q + base + (size_t)(q0s + warp * 32 + b * 16 + gid) * DIM;
            const float* q1 = q0 + 8 * DIM;
            #pragma unroll
            for (int ks = 0; ks < 4; ks++) {
                float2 v;
                v = *(const float2*)(q0 + ks * 16 + 2 * tig);
                qa[b][ks][0] = pack_h2(v.x * scale, v.y * scale);
                v = *(const float2*)(q1 + ks * 16 + 2 * tig);
                qa[b][ks][1] = pack_h2(v.x * scale, v.y * scale);
                v = *(const float2*)(q0 + ks * 16 + 2 * tig + 8);
                qa[b][ks][2] = pack_h2(v.x * scale, v.y * scale);
                v = *(const float2*)(q1 + ks * 16 + 2 * tig + 8);
                qa[b][ks][3] = pack_h2(v.x * scale, v.y * scale);
            }
        }
    }

    const int i0 = qt * 128 + warp * 32 + gid;
    const float aw[4] = { (float)i0        * (1.0f / 255.0f),
                          (float)(i0 + 8)  * (1.0f / 255.0f),
                          (float)(i0 + 16) * (1.0f / 255.0f),
                          (float)(i0 + 24) * (1.0f / 255.0f) };

    // prologue: depth-2 prefetch
    issue(0, 0);
    asm volatile("cp.async.commit_group;" ::: "memory");
    issue(1, 1);
    asm volatile("cp.async.commit_group;" ::: "memory");

    float dacc[2][8][4];
    #pragma unroll
    for (int b = 0; b < 2; b++)
        #pragma unroll
        for (int nt = 0; nt < 8; nt++)
            #pragma unroll
            for (int i = 0; i < 4; i++) dacc[b][nt][i] = 0.0f;
    float dden[2][4] = {{0,0,0,0},{0,0,0,0}};
    float s3[4] = {0,0,0,0};            // dden snapshot after chunk 3
    float s7[4] = {1,1,1,1};            // denp snapshot after chunk 7

    const int brow = gid * (KSTRIDE / 2) + tig;
    const int lrw  = warp * 32 + gid;

    for (int c = 0; c < nchunks; c++) {
        asm volatile("cp.async.wait_group 1;" ::: "memory");
        __syncthreads();                // chunk c resident

        const int st = c % NSTAGE;
        const uint32_t* sKu = (const uint32_t*)(dsm + st * STAGE_B);
        const uint32_t* sVu = (const uint32_t*)(dsm + st * STAGE_B + TILE_B);

        if (c + 2 < nchunks) issue(c + 2, (c + 2) % NSTAGE);
        asm volatile("cp.async.commit_group;" ::: "memory");

        // ---- phase A: MMA1 both row-blocks, K fragments loaded once ----
        uint32_t pa[2][4][4];
        #pragma unroll
        for (int nt = 0; nt < 8; nt++) {
            float sl0[4] = {0,0,0,0}, sl1[4] = {0,0,0,0};
            const int rb = nt * 8 * (KSTRIDE / 2) + brow;
            #pragma unroll
            for (int ks = 0; ks < 4; ks++) {
                const uint32_t b0 = sKu[rb + 8 * ks];
                const uint32_t b1 = sKu[rb + 8 * ks + 4];
                mma_f16(sl0, qa[0][ks], b0, b1);
                mma_f16(sl1, qa[1][ks], b0, b1);
            }
            const int kc = nt >> 1, hi = (nt & 1) * 2;
            pa[0][kc][hi]     = sigmoid_h2(sl0[0], sl0[1]);
            pa[0][kc][hi + 1] = sigmoid_h2(sl0[2], sl0[3]);
            pa[1][kc][hi]     = sigmoid_h2(sl1[0], sl1[1]);
            pa[1][kc][hi + 1] = sigmoid_h2(sl1[2], sl1[3]);
        }

        // ---- phase B: MMA2 both row-blocks + denominator MMAs ----
        #pragma unroll
        for (int kc = 0; kc < 4; kc++) {
            #pragma unroll
            for (int nt = 0; nt < 8; nt++) {
                const int rb = nt * 8 * (KSTRIDE / 2) + brow;
                const uint32_t b0 = sVu[rb + 8 * kc];
                const uint32_t b1 = sVu[rb + 8 * kc + 4];
                mma_f16(dacc[0][nt], pa[0][kc], b0, b1);
                mma_f16(dacc[1][nt], pa[1][kc], b0, b1);
            }
            mma_f16(dden[0], pa[0][kc], ONE_H2, ONE_H2);
            mma_f16(dden[1], pa[1][kc], ONE_H2, ONE_H2);
        }

        if (k > 0) {
            if (c == 3) {
                // stash A3 = D(0..3) as fp16; snapshot den(0..3); reset dacc
                s3[0] = dden[0][0]; s3[1] = dden[0][2];
                s3[2] = dden[1][0]; s3[3] = dden[1][2];
                #pragma unroll
                for (int b = 0; b < 2; b++)
                    #pragma unroll
                    for (int nt = 0; nt < 8; nt++) {
                        const int r0 = lrw + b * 16, r1 = r0 + 8;
                        xbuf[r0 * XSTRIDE_W + nt * 4 + tig] = pack_h2(dacc[b][nt][0], dacc[b][nt][1]);
                        xbuf[r1 * XSTRIDE_W + nt * 4 + tig] = pack_h2(dacc[b][nt][2], dacc[b][nt][3]);
                        dacc[b][nt][0] = 0.0f; dacc[b][nt][1] = 0.0f;
                        dacc[b][nt][2] = 0.0f; dacc[b][nt][3] = 0.0f;
                    }
            } else if (c == 7) {
                // stash <- A3 + dacc = D(0..7) = Dp; snapshot denp
                s7[0] = dden[0][0]; s7[1] = dden[0][2];
                s7[2] = dden[1][0]; s7[3] = dden[1][2];
                #pragma unroll
                for (int b = 0; b < 2; b++)
                    #pragma unroll
                    for (int nt = 0; nt < 8; nt++) {
                        const int r0 = lrw + b * 16, r1 = r0 + 8;
                        float2 f0 = __half22float2(*(__half2*)&xbuf[r0 * XSTRIDE_W + nt * 4 + tig]);
                        float2 f1 = __half22float2(*(__half2*)&xbuf[r1 * XSTRIDE_W + nt * 4 + tig]);
                        xbuf[r0 * XSTRIDE_W + nt * 4 + tig] = pack_h2(f0.x + dacc[b][nt][0], f0.y + dacc[b][nt][1]);
                        xbuf[r1 * XSTRIDE_W + nt * 4 + tig] = pack_h2(f1.x + dacc[b][nt][2], f1.y + dacc[b][nt][3]);
                    }
            }
        }
    }

    if (k == 0) {
        #pragma unroll
        for (int b = 0; b < 2; b++) {
            float* o0 = out + ((size_t)bh * SEQ + q0s + warp * 32 + b * 16 + gid) * DIM;
            float* o1 = o0 + 8 * DIM;
            const float inv0 = 1.0f / dden[b][0];
            const float inv1 = 1.0f / dden[b][2];
            #pragma unroll
            for (int nt = 0; nt < 8; nt++) {
                *(float2*)(o0 + nt * 8 + 2 * tig) = make_float2(dacc[b][nt][0] * inv0, dacc[b][nt][1] * inv0);
                *(float2*)(o1 + nt * 8 + 2 * tig) = make_float2(dacc[b][nt][2] * inv1, dacc[b][nt][3] * inv1);
            }
        }
    } else {
        // out = (1-a)/denp * Dp(stash) + a/denn * dacc,  denn = den_end - den(0..3)
        const float wp[4] = { (1.0f - aw[0]) / s7[0],
                              (1.0f - aw[1]) / s7[1],
                              (1.0f - aw[2]) / s7[2],
                              (1.0f - aw[3]) / s7[3] };
        const float wn[4] = { aw[0] / (dden[0][0] - s3[0]),
                              aw[1] / (dden[0][2] - s3[1]),
                              aw[2] / (dden[1][0] - s3[2]),
                              aw[3] / (dden[1][2] - s3[3]) };
        #pragma unroll
        for (int b = 0; b < 2; b++) {
            float* o0 = out + ((size_t)bh * SEQ + q0s + warp * 32 + b * 16 + gid) * DIM;
            float* o1 = o0 + 8 * DIM;
            const int r0 = lrw + b * 16, r1 = r0 + 8;
            #pragma unroll
            for (int nt = 0; nt < 8; nt++) {
                float2 f0 = __half22float2(*(__half2*)&xbuf[r0 * XSTRIDE_W + nt * 4 + tig]);
                float2 f1 = __half22float2(*(__half2*)&xbuf[r1 * XSTRIDE_W + nt * 4 + tig]);
                float2 out0 = { wp[2*b]   * f0.x + wn[2*b]   * dacc[b][nt][0],
                                wp[2*b]   * f0.y + wn[2*b]   * dacc[b][nt][1] };
                float2 out1 = { wp[2*b+1] * f1.x + wn[2*b+1] * dacc[b][nt][2],
                                wp[2*b+1] * f1.y + wn[2*b+1] * dacc[b][nt][3] };
                *(float2*)(o0 + nt * 8 + 2 * tig) = out0;
                *(float2*)(o1 + nt * 8 + 2 * tig) = out1;
            }
        }
    }
}

extern "C" void kernel_launch(void* const* d_in, const int* in_sizes, int n_in,
                              void* d_out, int out_size)
{
    const float* Q     = (const float*)d_in[0];
    const float* K     = (const float*)d_in[1];
    const float* V     = (const float*)d_in[2];
    const float* scale = (const float*)d_in[3];
    float* out = (float*)d_out;

    static bool attr_set = false;
    if (!attr_set) {
        cudaFuncSetAttribute(win_attn_m, cudaFuncAttributeMaxDynamicSharedMemorySize, SMEM_BYTES);
        attr_set = true;
    }

    dim3 pgrid(SEQ / 32, BH);
    prep_kv<<<pgrid, 256>>>(K, V);

    dim3 grid(NSEG * 2, BH);
    win_attn_m<<<grid, 128, SMEM_BYTES>>>(Q, scale, out);
}